// round 1
// baseline (speedup 1.0000x reference)
#include <cuda_runtime.h>

// PeriodicConvOp collapsed to a spatially-parameterized 3x3 conv:
//   out[b, co, 2hp+i, 2wp+j] =
//     sum_{cin,ky,kx} W[(g*8+o)*36 + cin*9 + ky*3 + kx]
//                     * x[b, cin, 2hp+gy+ky-1, 2wp+gx+kx-1]
//   g = co>>1, gy = co>>2, gx = (co>>1)&1, o = ((co&1)<<2) | (2i+j)
// All 4 outputs of a 2x2 quad share the same (shifted) 3x3 input window;
// only the weights differ per (i,j).

#define CIN   4
#define COUT  8
#define HH    512
#define WW    512

#define TILE_H 32          // output rows per block
#define TILE_W 64          // output cols per block
#define SROWS  (TILE_H + 2)   // 34 input rows  (h0-1 .. h0+32)
#define SCOLS  (TILE_W + 4)   // 68 input cols  (w0-2 .. w0+65)
#define SX_FLOATS (CIN * SROWS * SCOLS)     // 9248
#define SW_FLOATS (COUT * CIN * 4 * 9)      // 1152

#define NQ 4               // vertical quads per thread
#define NTHREADS 128       // 4 warps; warp covers NQ quad-rows, lane -> quad col

// Compile-time GX so every register-array index is constant (no LMEM).
template<int GX>
__device__ __forceinline__ void compute_gx(
    const float* __restrict__ sx,      // smem input tile base
    const float* __restrict__ swco,    // smem weights for this co: [cin][m][9]
    float (&acc)[NQ][2][2],
    int gy, int Q0, int lane)
{
    #pragma unroll
    for (int cin = 0; cin < CIN; ++cin) {
        // 36 weights for this (co,cin): m-major, tap-minor. 9x LDS.128 broadcast.
        const float* swc = swco + cin * 36;
        float w[36];
        #pragma unroll
        for (int t = 0; t < 9; ++t) {
            float4 v = reinterpret_cast<const float4*>(swc)[t];
            w[4*t+0] = v.x; w[4*t+1] = v.y; w[4*t+2] = v.z; w[4*t+3] = v.w;
        }

        // Input column base: cidx = 2*lane + 2*GX, window col cc = kx + 1 - GX.
        const float* base = sx + cin * (SROWS * SCOLS) + 2 * lane + 2 * GX;

        float win[3][4];   // 3 rows x 4 cols rolling window
        #pragma unroll
        for (int q = 0; q < NQ; ++q) {
            const int r0 = 2 * (Q0 + q) + gy;   // smem row for ky=0
            if (q == 0) {
                #pragma unroll
                for (int rr = 0; rr < 3; ++rr) {
                    const float* p = base + (r0 + rr) * SCOLS;
                    float2 a = *reinterpret_cast<const float2*>(p);
                    float2 b = *reinterpret_cast<const float2*>(p + 2);
                    win[rr][0] = a.x; win[rr][1] = a.y;
                    win[rr][2] = b.x; win[rr][3] = b.y;
                }
            } else {
                // rows shift by 2: old row r0+2 becomes new row r0+0
                #pragma unroll
                for (int c = 0; c < 4; ++c) win[0][c] = win[2][c];
                #pragma unroll
                for (int rr = 1; rr < 3; ++rr) {
                    const float* p = base + (r0 + rr) * SCOLS;
                    float2 a = *reinterpret_cast<const float2*>(p);
                    float2 b = *reinterpret_cast<const float2*>(p + 2);
                    win[rr][0] = a.x; win[rr][1] = a.y;
                    win[rr][2] = b.x; win[rr][3] = b.y;
                }
            }
            // 4 quad outputs share the window; 36 FMAs
            #pragma unroll
            for (int i = 0; i < 2; ++i)
                #pragma unroll
                for (int j = 0; j < 2; ++j)
                    #pragma unroll
                    for (int ky = 0; ky < 3; ++ky)
                        #pragma unroll
                        for (int kx = 0; kx < 3; ++kx)
                            acc[q][i][j] = fmaf(w[(2*i+j)*9 + ky*3 + kx],
                                                win[ky][kx + 1 - GX],
                                                acc[q][i][j]);
        }
    }
}

__global__ void __launch_bounds__(NTHREADS)
periodic_conv_kernel(const float* __restrict__ x,
                     const float* __restrict__ wt,
                     float* __restrict__ out)
{
    __shared__ float sx[SX_FLOATS];
    __shared__ float sw[SW_FLOATS];

    const int b   = blockIdx.z;
    const int h0  = blockIdx.y * TILE_H;
    const int w0  = blockIdx.x * TILE_W;
    const int tid = threadIdx.x;

    // ---- weights: repack to [co][cin][m][tap] ----
    for (int d = tid; d < SW_FLOATS; d += NTHREADS) {
        int co  = d / 144;
        int r   = d - co * 144;
        int cin = r / 36;
        int r2  = r - cin * 36;
        int m   = r2 / 9;
        int t   = r2 - m * 9;
        int g   = co >> 1;
        int o   = ((co & 1) << 2) | m;
        sw[d] = wt[(g * 8 + o) * 36 + cin * 9 + t];
    }

    // ---- input tile with zero-padded halo ----
    for (int d = tid; d < SX_FLOATS; d += NTHREADS) {
        int cin = d / (SROWS * SCOLS);
        int rem = d - cin * (SROWS * SCOLS);
        int r   = rem / SCOLS;
        int c   = rem - r * SCOLS;
        int gr  = h0 - 1 + r;
        int gc  = w0 - 2 + c;
        float v = 0.f;
        if ((unsigned)gr < (unsigned)HH && (unsigned)gc < (unsigned)WW)
            v = x[((b * CIN + cin) * HH + gr) * WW + gc];
        sx[d] = v;
    }
    __syncthreads();

    const int lane = tid & 31;
    const int wid  = tid >> 5;
    const int Q0   = wid * NQ;    // first quad-row of this warp (block-local)

    #pragma unroll 1
    for (int co = 0; co < COUT; ++co) {
        const int gy = co >> 2;
        const int gx = (co >> 1) & 1;

        float acc[NQ][2][2];
        #pragma unroll
        for (int q = 0; q < NQ; ++q)
            #pragma unroll
            for (int i = 0; i < 2; ++i)
                #pragma unroll
                for (int j = 0; j < 2; ++j)
                    acc[q][i][j] = 0.f;

        const float* swco = sw + co * (CIN * 36);
        if (gx == 0) compute_gx<0>(sx, swco, acc, gy, Q0, lane);
        else         compute_gx<1>(sx, swco, acc, gy, Q0, lane);

        // ---- store: float2 per (quad,row), coalesced across lanes ----
        #pragma unroll
        for (int q = 0; q < NQ; ++q) {
            #pragma unroll
            for (int i = 0; i < 2; ++i) {
                int row = h0 + 2 * (Q0 + q) + i;
                float2 v = make_float2(acc[q][i][0], acc[q][i][1]);
                *reinterpret_cast<float2*>(
                    &out[((size_t)(b * COUT + co) * HH + row) * WW + w0 + 2 * lane]) = v;
            }
        }
    }
}

extern "C" void kernel_launch(void* const* d_in, const int* in_sizes, int n_in,
                              void* d_out, int out_size)
{
    const float* x  = (const float*)d_in[0];
    const float* wt = (const float*)d_in[1];
    float* out      = (float*)d_out;

    int B = in_sizes[0] / (CIN * HH * WW);   // 8

    dim3 grid(WW / TILE_W, HH / TILE_H, B);  // (8, 16, 8) = 1024 blocks
    periodic_conv_kernel<<<grid, NTHREADS>>>(x, wt, out);
}

// round 4
// speedup vs baseline: 1.0355x; 1.0355x over previous
#include <cuda_runtime.h>

// PeriodicConvOp collapsed to a spatially-parameterized 3x3 conv:
//   out[b, co, 2hp+i, 2wp+j] =
//     sum_{cin,ky,kx} W[(g*8+o)*36 + cin*9 + ky*3 + kx]
//                     * x[b, cin, 2hp+gy+ky-1, 2wp+gx+kx-1]
//   g = co>>1, gy = co>>2, gx = (co>>1)&1, o = ((co&1)<<2) | m, m = 2i+j
//
// Structure:
//  - One 4x4 per-thread window (rows 2q+gy+ky, cols 2lane+gx+kx) serves ALL
//    8 output channels (co pairs share samples exactly; groups g are shifts).
//  - Channel pairs (2g, 2g+1) are computed with packed fma.rn.f32x2 (FFMA2):
//    weights interleaved (lo=even co, hi=odd co), inputs broadcast-packed.

#define CIN   4
#define COUT  8
#define HH    512
#define WW    512

#define TILE_H 16          // output rows per block
#define TILE_W 64          // output cols per block
#define SROWS  (TILE_H + 2)   // 18 input rows  (h0-1 .. h0+16)
#define SCOLS  (TILE_W + 2)   // 66 input cols  (w0-1 .. w0+64)
#define SX_FLOATS (CIN * SROWS * SCOLS)     // 4752

#define WPAIR_STRIDE 10    // float2 slots per (g,cin,m): 9 taps + 1 pad (16B-aligned rows)
#define SW_FLOATS (4 * CIN * 4 * WPAIR_STRIDE * 2)   // 1280 floats

#define NQ 2               // quad-rows per warp
#define NTHREADS 128       // 4 warps; block = 8 quad rows x 32 quad cols

typedef unsigned long long ull;

__device__ __forceinline__ ull pack2(float v) {
    ull r; asm("mov.b64 %0, {%1, %1};" : "=l"(r) : "f"(v)); return r;
}
__device__ __forceinline__ void unpack2(ull v, float& lo, float& hi) {
    asm("mov.b64 {%0, %1}, %2;" : "=f"(lo), "=f"(hi) : "l"(v));
}
__device__ __forceinline__ void fma2(ull& d, ull a, ull b) {
    asm("fma.rn.f32x2 %0, %1, %2, %0;" : "+l"(d) : "l"(a), "l"(b));
}

__global__ void __launch_bounds__(NTHREADS)
periodic_conv_kernel(const float* __restrict__ x,
                     const float* __restrict__ wt,
                     float* __restrict__ out)
{
    __shared__ __align__(16) float sx[SX_FLOATS];
    __shared__ __align__(16) float sw2[SW_FLOATS];

    const int b   = blockIdx.z;
    const int h0  = blockIdx.y * TILE_H;
    const int w0  = blockIdx.x * TILE_W;
    const int tid = threadIdx.x;

    // ---- weights: pack channel pairs. entry d = ((g*4+cin)*4+m)*10 + t ----
    for (int d = tid; d < 4 * CIN * 4 * WPAIR_STRIDE; d += NTHREADS) {
        int t   = d % WPAIR_STRIDE;
        int r   = d / WPAIR_STRIDE;
        int m   = r & 3;  r >>= 2;
        int cin = r & 3;
        int g   = r >> 2;
        float lo = 0.f, hi = 0.f;
        if (t < 9) {
            lo = wt[(g * 8 + m    ) * 36 + cin * 9 + t];   // co = 2g   (o = m)
            hi = wt[(g * 8 + m + 4) * 36 + cin * 9 + t];   // co = 2g+1 (o = m+4)
        }
        sw2[2 * d]     = lo;
        sw2[2 * d + 1] = hi;
    }

    // ---- input tile with zero-padded halo (origin: h0-1, w0-1) ----
    for (int d = tid; d < SX_FLOATS; d += NTHREADS) {
        int cin = d / (SROWS * SCOLS);
        int rem = d - cin * (SROWS * SCOLS);
        int r   = rem / SCOLS;
        int c   = rem - r * SCOLS;
        int gr  = h0 - 1 + r;
        int gc  = w0 - 1 + c;
        float v = 0.f;
        if ((unsigned)gr < (unsigned)HH && (unsigned)gc < (unsigned)WW)
            v = x[((b * CIN + cin) * HH + gr) * WW + gc];
        sx[d] = v;
    }
    __syncthreads();

    const int lane = tid & 31;
    const int wid  = tid >> 5;
    const int Q0   = wid * NQ;    // first (block-local) quad-row of this warp

    // acc[g][m][q]: lo = co 2g, hi = co 2g+1; m = 2i+j
    ull acc[4][4][NQ];
    #pragma unroll
    for (int g = 0; g < 4; ++g)
        #pragma unroll
        for (int m = 0; m < 4; ++m)
            #pragma unroll
            for (int q = 0; q < NQ; ++q)
                acc[g][m][q] = 0ull;

    #pragma unroll 1
    for (int cin = 0; cin < CIN; ++cin) {
        // Window for both quad rows: smem rows 2*Q0 .. 2*Q0+5, cols 2*lane .. 2*lane+3.
        // winp[rr][c] = packed (v,v); used as winp[2q+gy+ky][gx+kx].
        ull winp[6][4];
        const float* basex = sx + cin * (SROWS * SCOLS) + 2 * Q0 * SCOLS + 2 * lane;
        #pragma unroll
        for (int rr = 0; rr < 6; ++rr) {
            float2 a  = *reinterpret_cast<const float2*>(basex + rr * SCOLS);
            float2 c2 = *reinterpret_cast<const float2*>(basex + rr * SCOLS + 2);
            winp[rr][0] = pack2(a.x);  winp[rr][1] = pack2(a.y);
            winp[rr][2] = pack2(c2.x); winp[rr][3] = pack2(c2.y);
        }

        #pragma unroll
        for (int g = 0; g < 4; ++g) {
            const int gy = g >> 1;
            const int gx = g & 1;
            #pragma unroll
            for (int m = 0; m < 4; ++m) {
                // 9 packed weight pairs via 5x LDS.128 (broadcast)
                const ulonglong2* wp = reinterpret_cast<const ulonglong2*>(
                    sw2 + ((g * 4 + cin) * 4 + m) * (2 * WPAIR_STRIDE));
                ull w[10];
                #pragma unroll
                for (int t = 0; t < 5; ++t) {
                    ulonglong2 v = wp[t];
                    w[2 * t] = v.x; w[2 * t + 1] = v.y;
                }
                #pragma unroll
                for (int q = 0; q < NQ; ++q)
                    #pragma unroll
                    for (int ky = 0; ky < 3; ++ky)
                        #pragma unroll
                        for (int kx = 0; kx < 3; ++kx)
                            fma2(acc[g][m][q],
                                 w[ky * 3 + kx],
                                 winp[2 * q + gy + ky][gx + kx]);
            }
        }
    }

    // ---- store: per (g, q, i) one float2 row-segment per channel of the pair ----
    #pragma unroll
    for (int g = 0; g < 4; ++g) {
        #pragma unroll
        for (int q = 0; q < NQ; ++q) {
            #pragma unroll
            for (int i = 0; i < 2; ++i) {
                float lo0, hi0, lo1, hi1;
                unpack2(acc[g][2 * i    ][q], lo0, hi0);   // j = 0
                unpack2(acc[g][2 * i + 1][q], lo1, hi1);   // j = 1
                const int row = h0 + 2 * (Q0 + q) + i;
                size_t base0 = ((size_t)(b * COUT + 2 * g) * HH + row) * WW + w0 + 2 * lane;
                size_t base1 = base0 + (size_t)HH * WW;
                *reinterpret_cast<float2*>(&out[base0]) = make_float2(lo0, lo1);
                *reinterpret_cast<float2*>(&out[base1]) = make_float2(hi0, hi1);
            }
        }
    }
}

extern "C" void kernel_launch(void* const* d_in, const int* in_sizes, int n_in,
                              void* d_out, int out_size)
{
    const float* x  = (const float*)d_in[0];
    const float* wt = (const float*)d_in[1];
    float* out      = (float*)d_out;

    int B = in_sizes[0] / (CIN * HH * WW);   // 8

    dim3 grid(WW / TILE_W, HH / TILE_H, B);  // (8, 32, 8) = 2048 blocks
    periodic_conv_kernel<<<grid, NTHREADS>>>(x, wt, out);
}